// round 3
// baseline (speedup 1.0000x reference)
#include <cuda_runtime.h>
#include <cstdint>

#define N_NODES 50000
#define N_EDGES 1600000
#define HID 64
#define DM 64
#define NV 16
#define SCAN_BLK 1024
#define SCAN_NB ((N_NODES + SCAN_BLK - 1) / SCAN_BLK)   // 49

// ---------------- scratch (no allocations allowed) ----------------
__device__ float g_h0[N_NODES * HID];
__device__ float g_h1[N_NODES * HID];
__device__ int   g_cnt[N_NODES];
__device__ int   g_cursor[N_NODES];
__device__ int   g_off[N_NODES + 1];
__device__ int   g_bucket[N_EDGES];
__device__ int   g_bsum[SCAN_NB];
__device__ int   g_bsumx[SCAN_NB];
__device__ float g_A4[HID * 4];          // per j: A[j][0..2], ca[j]
__device__ float g_W1dup[HID * 2 * HID]; // [k][2j]=(W1[j][k],W1[j][k])

// packed f32x2 helpers
#define PACK2(d, lo, hi)  asm("mov.b64 %0,{%1,%2};" : "=l"(d) : "f"(lo), "f"(hi))
#define UNPACK2(lo, hi, s) asm("mov.b64 {%0,%1},%2;" : "=f"(lo), "=f"(hi) : "l"(s))
#define FMA2(d, a, b, c)  asm("fma.rn.f32x2 %0,%1,%2,%3;" : "=l"(d) : "l"(a), "l"(b), "l"(c))

// ---------------- K0: fold Wa/We/be/vnf_mean/ba into A (64x3) + ca (64) ------
__global__ void precompute_kernel(const float* __restrict__ Wa,
                                  const float* __restrict__ ba,
                                  const float* __restrict__ We,
                                  const float* __restrict__ be,
                                  const float* __restrict__ env) {
    __shared__ float vnfm[DM];
    __shared__ float bes[HID];
    int j = threadIdx.x;   // 64 threads
    float m = 0.f;
    for (int i = 0; i < NV; i++) m += env[i * DM + j];
    vnfm[j] = m * (1.0f / NV);
    bes[j] = be[j];
    __syncthreads();

    const float* row = Wa + j * (HID + DM);
    float c = ba[j], a0 = 0.f, a1 = 0.f, a2 = 0.f;
    #pragma unroll 8
    for (int k = 0; k < HID; k++) {
        float w = row[k];
        c  = fmaf(w, bes[k], c);
        a0 = fmaf(w, We[k * 3 + 0], a0);
        a1 = fmaf(w, We[k * 3 + 1], a1);
        a2 = fmaf(w, We[k * 3 + 2], a2);
    }
    #pragma unroll 8
    for (int d = 0; d < DM; d++) c = fmaf(row[HID + d], vnfm[d], c);
    g_A4[j * 4 + 0] = a0;
    g_A4[j * 4 + 1] = a1;
    g_A4[j * 4 + 2] = a2;
    g_A4[j * 4 + 3] = c;
}

// ---------------- K0b: transpose+duplicate W1 into global scratch -------------
__global__ void w1dup_kernel(const float* __restrict__ W1) {
    int i = blockIdx.x * blockDim.x + threadIdx.x;   // 4096 threads total
    if (i < HID * HID) {
        int j = i >> 6, k = i & 63;
        float w = W1[i];                 // coalesced read
        g_W1dup[k * 128 + 2 * j]     = w;
        g_W1dup[k * 128 + 2 * j + 1] = w;
    }
}

// ---------------- K1: node_fc  h0 = nf @ Wn^T + bn --------------------------
__global__ void node_fc_kernel(const float* __restrict__ nf,
                               const float* __restrict__ Wn,
                               const float* __restrict__ bn) {
    __shared__ float ws[HID * 3];
    __shared__ float bs[HID];
    int t = threadIdx.x;
    if (t < HID * 3) ws[t] = Wn[t];
    if (t < HID) bs[t] = bn[t];
    __syncthreads();
    int idx = blockIdx.x * blockDim.x + t;       // N*64 threads
    int i = idx >> 6, j = idx & 63;
    const float* r = nf + i * 3;
    float v = fmaf(ws[j * 3 + 0], r[0],
              fmaf(ws[j * 3 + 1], r[1],
              fmaf(ws[j * 3 + 2], r[2], bs[j])));
    g_h0[idx] = v;
}

// ---------------- K2: zero counters -----------------------------------------
__global__ void zero_kernel() {
    int i = blockIdx.x * blockDim.x + threadIdx.x;
    if (i < N_NODES) g_cnt[i] = 0;
}

// ---------------- K3: degree count ------------------------------------------
__global__ void count_kernel(const int* __restrict__ src) {
    int e = blockIdx.x * blockDim.x + threadIdx.x;   // exact E threads
    atomicAdd(&g_cnt[src[e]], 1);
}

// ---------------- K4a/b/c: 3-phase exclusive scan of g_cnt -------------------
__global__ void scanA_kernel() {
    __shared__ int sh[SCAN_BLK];
    int t = threadIdx.x;
    int gid = blockIdx.x * SCAN_BLK + t;
    int v = (gid < N_NODES) ? g_cnt[gid] : 0;
    sh[t] = v;
    __syncthreads();
    for (int o = 1; o < SCAN_BLK; o <<= 1) {
        int y = (t >= o) ? sh[t - o] : 0;
        __syncthreads();
        sh[t] += y;
        __syncthreads();
    }
    if (gid < N_NODES) g_off[gid] = sh[t] - v;   // block-local exclusive
    if (t == SCAN_BLK - 1) g_bsum[blockIdx.x] = sh[t];
}

__global__ void scanB_kernel() {
    __shared__ int sh[64];
    int t = threadIdx.x;   // 64 threads
    int v = (t < SCAN_NB) ? g_bsum[t] : 0;
    sh[t] = v;
    __syncthreads();
    for (int o = 1; o < 64; o <<= 1) {
        int y = (t >= o) ? sh[t - o] : 0;
        __syncthreads();
        sh[t] += y;
        __syncthreads();
    }
    if (t < SCAN_NB) g_bsumx[t] = sh[t] - v;
    if (t == SCAN_NB - 1) g_off[N_NODES] = sh[t];
}

__global__ void scanC_kernel() {
    int gid = blockIdx.x * SCAN_BLK + threadIdx.x;
    if (gid < N_NODES) {
        int o = g_off[gid] + g_bsumx[blockIdx.x];
        g_off[gid] = o;
        g_cursor[gid] = o;       // bucket cursor starts at CSR offset
    }
}

// ---------------- K5: bucket fill (CSR adjacency, single atomic) --------------
__global__ void bucket_kernel(const int* __restrict__ src,
                              const int* __restrict__ dst) {
    int e = blockIdx.x * blockDim.x + threadIdx.x;
    int p = atomicAdd(&g_cursor[src[e]], 1);
    g_bucket[p] = dst[e];
}

// ---------------- K6: GraphSAGE layer (warp per node, float2 gather) ----------
__global__ __launch_bounds__(256)
void sage_layer_kernel(const float* __restrict__ hin,
                       float* __restrict__ hout,
                       const float* __restrict__ Wself,
                       const float* __restrict__ bself,
                       const float* __restrict__ Wneigh,
                       const float* __restrict__ bneigh) {
    __shared__ float wsT[HID * HID];   // transposed: wsT[k*64+j]
    __shared__ float wnT[HID * HID];
    __shared__ float stage[8][2 * HID];
    __shared__ float bs[HID], bn2[HID];
    int t = threadIdx.x;
    for (int i = t; i < HID * HID; i += 256) {
        int j = i >> 6, k = i & 63;
        wsT[k * HID + j] = Wself[i];
        wnT[k * HID + j] = Wneigh[i];
    }
    if (t < HID) { bs[t] = bself[t]; bn2[t] = bneigh[t]; }
    __syncthreads();

    int w = t >> 5, lane = t & 31;
    for (int node = blockIdx.x * 8 + w; node < N_NODES; node += gridDim.x * 8) {
        const float2* hrow2 = (const float2*)(hin + node * HID);
        float2 sv = hrow2[lane];
        float ax = 0.f, ay = 0.f;
        int b = g_off[node], e2 = g_off[node + 1];
        #pragma unroll 4
        for (int idx = b; idx < e2; idx++) {
            const float2* hn2 = (const float2*)(hin + g_bucket[idx] * HID);
            float2 nv = hn2[lane];
            ax += nv.x;
            ay += nv.y;
        }
        int c = e2 - b;
        float inv = 1.0f / (float)(c > 0 ? c : 1);
        ax *= inv; ay *= inv;

        stage[w][2 * lane] = sv.x;       stage[w][2 * lane + 1] = sv.y;
        stage[w][64 + 2 * lane] = ax;    stage[w][64 + 2 * lane + 1] = ay;
        __syncwarp();

        float olo = bs[lane] + bn2[lane];
        float ohi = bs[lane + 32] + bn2[lane + 32];
        #pragma unroll 8
        for (int k = 0; k < HID; k++) {
            float hv = stage[w][k];
            float nv = stage[w][64 + k];
            olo = fmaf(wsT[k * HID + lane], hv, fmaf(wnT[k * HID + lane], nv, olo));
            ohi = fmaf(wsT[k * HID + 32 + lane], hv, fmaf(wnT[k * HID + 32 + lane], nv, ohi));
        }
        hout[node * HID + lane]      = fmaxf(olo, 0.f);
        hout[node * HID + 32 + lane] = fmaxf(ohi, 0.f);
        __syncwarp();
    }
}

// ---------------- K7: edge scorer, register-tiled (128 edges/block) -----------
// Thread layout: c = t&7 (8 output-groups of 8 j), r = t>>3 (16 edge-groups of 8)
// SMEM: A4s[64]f4 | actT[64][128] | w1dup[64][128] | red[8][128] | b1s | w2s
#define EDGE_SMEM_FLOATS (256 + 8192 + 8192 + 1024 + 64 + 64)

__global__ __launch_bounds__(128)
void edge_score_kernel(const float* __restrict__ ef,
                       const float* __restrict__ b1,
                       const float* __restrict__ W2,
                       const float* __restrict__ b2,
                       float* __restrict__ out) {
    extern __shared__ float smemf[];
    float4* A4s  = (float4*)smemf;            // 64 float4 = 256 floats
    float*  actT = smemf + 256;               // [64][128]
    float*  w1d  = actT + 8192;               // [64][128]
    float*  red  = w1d + 8192;                // [8][128]
    float*  b1s  = red + 1024;                // 64
    float*  w2s  = b1s + 64;                  // 64

    int t = threadIdx.x;
    if (t < 64) {
        A4s[t] = ((const float4*)g_A4)[t];
        b1s[t] = b1[t];
        w2s[t] = W2[t];
    }
    for (int i = t; i < 8192; i += 128) w1d[i] = g_W1dup[i];   // coalesced
    __syncthreads();

    // stage 1: per-thread edge activation into transposed SMEM (relu applied)
    {
        int e = blockIdx.x * 128 + t;
        const float* p = ef + e * 3;
        float x = p[0], y = p[1], z = p[2];
        #pragma unroll
        for (int k = 0; k < 64; k++) {
            float4 cc = A4s[k];
            float v = fmaf(cc.x, x, fmaf(cc.y, y, fmaf(cc.z, z, cc.w)));
            actT[k * 128 + t] = fmaxf(v, 0.f);
        }
    }
    __syncthreads();

    // stage 2: 8 edges x 8 outputs register tile over k=0..63
    int c = t & 7, r = t >> 3;
    unsigned long long acc[4][8];
    #pragma unroll
    for (int p = 0; p < 4; p++)
        #pragma unroll
        for (int q = 0; q < 8; q++) acc[p][q] = 0ULL;

    const char* aBase = (const char*)actT + r * 32;   // 4 f32x2 = 8 edges
    const char* wBase = (const char*)w1d  + c * 64;   // 8 f32x2 dup weights

    #pragma unroll 2
    for (int k = 0; k < 64; k++) {
        ulonglong2 la0 = *(const ulonglong2*)(aBase + k * 512);
        ulonglong2 la1 = *(const ulonglong2*)(aBase + k * 512 + 16);
        ulonglong2 lw0 = *(const ulonglong2*)(wBase + k * 512);
        ulonglong2 lw1 = *(const ulonglong2*)(wBase + k * 512 + 16);
        ulonglong2 lw2 = *(const ulonglong2*)(wBase + k * 512 + 32);
        ulonglong2 lw3 = *(const ulonglong2*)(wBase + k * 512 + 48);
        unsigned long long av[4] = {la0.x, la0.y, la1.x, la1.y};
        unsigned long long wv[8] = {lw0.x, lw0.y, lw1.x, lw1.y,
                                    lw2.x, lw2.y, lw3.x, lw3.y};
        #pragma unroll
        for (int p = 0; p < 4; p++)
            #pragma unroll
            for (int q = 0; q < 8; q++)
                FMA2(acc[p][q], av[p], wv[q], acc[p][q]);
    }

    // epilogue: bias + relu + scorer dot, reduce partials across c
    float part[8];
    #pragma unroll
    for (int i = 0; i < 8; i++) part[i] = 0.f;
    #pragma unroll
    for (int q = 0; q < 8; q++) {
        int j = c * 8 + q;
        float bb = b1s[j], ws = w2s[j];
        #pragma unroll
        for (int p = 0; p < 4; p++) {
            float lo, hi;
            UNPACK2(lo, hi, acc[p][q]);
            part[2 * p]     = fmaf(fmaxf(lo + bb, 0.f), ws, part[2 * p]);
            part[2 * p + 1] = fmaf(fmaxf(hi + bb, 0.f), ws, part[2 * p + 1]);
        }
    }
    #pragma unroll
    for (int i = 0; i < 8; i++) red[c * 128 + r * 8 + i] = part[i];
    __syncthreads();

    float s = b2[0];
    #pragma unroll
    for (int q = 0; q < 8; q++) s += red[q * 128 + t];
    out[blockIdx.x * 128 + t] = s;
}

// ---------------- launch ------------------------------------------------------
extern "C" void kernel_launch(void* const* d_in, const int* in_sizes, int n_in,
                              void* d_out, int out_size) {
    const float* node_feats = (const float*)d_in[0];
    const float* edge_feats = (const float*)d_in[1];
    const float* env        = (const float*)d_in[2];
    const int*   edge_index = (const int*)d_in[3];
    const float* Wn  = (const float*)d_in[4];
    const float* bn  = (const float*)d_in[5];
    const float* We  = (const float*)d_in[6];
    const float* be  = (const float*)d_in[7];
    const float* Wself  = (const float*)d_in[8];
    const float* bself  = (const float*)d_in[9];
    const float* Wneigh = (const float*)d_in[10];
    const float* bneigh = (const float*)d_in[11];
    const float* Wa  = (const float*)d_in[12];
    const float* ba  = (const float*)d_in[13];
    const float* W1  = (const float*)d_in[14];
    const float* b1  = (const float*)d_in[15];
    const float* W2  = (const float*)d_in[16];
    const float* b2  = (const float*)d_in[17];

    float* out_scores = (float*)d_out;             // [E]
    float* out_h = (float*)d_out + N_EDGES;        // [N, H]

    const int* src = edge_index;
    const int* dst = edge_index + N_EDGES;

    float* h0p; cudaGetSymbolAddress((void**)&h0p, g_h0);
    float* h1p; cudaGetSymbolAddress((void**)&h1p, g_h1);

    cudaFuncSetAttribute(edge_score_kernel,
                         cudaFuncAttributeMaxDynamicSharedMemorySize,
                         EDGE_SMEM_FLOATS * 4);

    precompute_kernel<<<1, 64>>>(Wa, ba, We, be, env);
    w1dup_kernel<<<16, 256>>>(W1);
    node_fc_kernel<<<(N_NODES * HID) / 256, 256>>>(node_feats, Wn, bn);
    zero_kernel<<<(N_NODES + 255) / 256, 256>>>();
    count_kernel<<<N_EDGES / 256, 256>>>(src);
    scanA_kernel<<<SCAN_NB, SCAN_BLK>>>();
    scanB_kernel<<<1, 64>>>();
    scanC_kernel<<<SCAN_NB, SCAN_BLK>>>();
    bucket_kernel<<<N_EDGES / 256, 256>>>(src, dst);

    sage_layer_kernel<<<(N_NODES + 7) / 8, 256>>>(h0p, h1p,
        Wself, bself, Wneigh, bneigh);
    sage_layer_kernel<<<(N_NODES + 7) / 8, 256>>>(h1p, out_h,
        Wself + HID * HID, bself + HID, Wneigh + HID * HID, bneigh + HID);

    edge_score_kernel<<<N_EDGES / 128, 128, EDGE_SMEM_FLOATS * 4>>>(
        edge_feats, b1, W2, b2, out_scores);
}